// round 2
// baseline (speedup 1.0000x reference)
#include <cuda_runtime.h>

// Problem constants
#define NPOS      65536      // 16 * 64 * 64 positions
#define SPATIAL   4096       // 64 * 64
#define BATCH     16
#define DIM       64         // embedding dim
#define NCODES    1024
#define CODES_PER_TILE 128
#define Q_ELEMS   4194304    // 16*64*64*64
#define OUT_LOSS_OFF 0
#define OUT_Q_OFF    1
#define OUT_IDX_OFF  (1 + Q_ELEMS)

__device__ float g_ebias[NCODES];   // 0.5 * ||e_k||^2

// ---------------------------------------------------------------------------
// Kernel 0: zero the loss accumulator (d_out poisoned to 0xAA by harness)
// ---------------------------------------------------------------------------
__global__ void vq_init_kernel(float* out) {
    if (threadIdx.x == 0 && blockIdx.x == 0) out[OUT_LOSS_OFF] = 0.0f;
}

// ---------------------------------------------------------------------------
// Kernel 1: ebias[k] = 0.5 * sum_c e[k][c]^2
// ---------------------------------------------------------------------------
__global__ void vq_ebias_kernel(const float* __restrict__ emb) {
    int k = blockIdx.x * blockDim.x + threadIdx.x;
    if (k >= NCODES) return;
    const float4* row = (const float4*)(emb + (size_t)k * DIM);
    float s = 0.0f;
#pragma unroll
    for (int j = 0; j < DIM / 4; j++) {
        float4 v = row[j];
        s += v.x * v.x + v.y * v.y + v.z * v.z + v.w * v.w;
    }
    g_ebias[k] = 0.5f * s;
}

// ---------------------------------------------------------------------------
// Kernel 2: main VQ kernel.
// One thread per spatial position. x (64 floats) held in 32 packed f32x2
// registers; codes streamed through shared memory in tiles of 128; the dot
// product runs on fma.rn.f32x2 (2 FMA/instr). Epilogue: gather quantized,
// write index, accumulate commitment loss.
// ---------------------------------------------------------------------------
__global__ __launch_bounds__(128, 4) void vq_main_kernel(
    const float* __restrict__ x_in,   // [16, 64, 64, 64] NCHW
    const float* __restrict__ emb,    // [1024, 64]
    float* __restrict__ out)
{
    const int n = blockIdx.x * blockDim.x + threadIdx.x;  // position id
    const int b = n >> 12;          // / 4096
    const int s = n & 4095;         // h*64 + w
    const float* xp = x_in + (size_t)b * (DIM * SPATIAL) + s;

    // Load x: x[c] = xp[c * SPATIAL]; pack (c even, c odd) into f32x2.
    // For a warp, consecutive threads -> consecutive s -> coalesced per c.
    unsigned long long x2[DIM / 2];
#pragma unroll
    for (int j = 0; j < DIM / 2; j++) {
        float lo = xp[(2 * j)     * SPATIAL];
        float hi = xp[(2 * j + 1) * SPATIAL];
        asm("mov.b64 %0, {%1, %2};" : "=l"(x2[j]) : "f"(lo), "f"(hi));
    }

    __shared__ float se[CODES_PER_TILE * DIM];     // 32 KB code tile
    __shared__ float sbias[CODES_PER_TILE];

    float best  = 3.402823466e38f;
    int   bestk = 0;

    for (int t = 0; t < NCODES / CODES_PER_TILE; t++) {
        __syncthreads();
        // Cooperative, coalesced tile load (8192 floats via float4).
        {
            const float4* src = (const float4*)(emb + (size_t)t * CODES_PER_TILE * DIM);
            float4* dst = (float4*)se;
#pragma unroll
            for (int i = threadIdx.x; i < CODES_PER_TILE * DIM / 4; i += 128)
                dst[i] = src[i];
            sbias[threadIdx.x] = g_ebias[t * CODES_PER_TILE + threadIdx.x];
        }
        __syncthreads();

#pragma unroll 2
        for (int k = 0; k < CODES_PER_TILE; k++) {
            const unsigned long long* e2 =
                (const unsigned long long*)(se + k * DIM);   // broadcast reads
            unsigned long long acc = 0ULL;   // packed (0.f, 0.f)
#pragma unroll
            for (int j = 0; j < DIM / 2; j++) {
                asm("fma.rn.f32x2 %0, %1, %2, %0;"
                    : "+l"(acc) : "l"(x2[j]), "l"(e2[j]));
            }
            float alo, ahi;
            asm("mov.b64 {%0, %1}, %2;" : "=f"(alo), "=f"(ahi) : "l"(acc));
            float score = sbias[k] - (alo + ahi);   // 0.5||e||^2 - x.e
            if (score < best) { best = score; bestk = t * CODES_PER_TILE + k; }
        }
    }

    // ---- Epilogue: gather quantized (NCHW), index, commitment loss ----
    const float* eb = emb + (size_t)bestk * DIM;   // L1/L2-resident (256 KB table)
    float* q = out + OUT_Q_OFF + (size_t)b * (DIM * SPATIAL) + s;

    float lsum = 0.0f;
#pragma unroll
    for (int j = 0; j < DIM / 2; j++) {
        float xlo, xhi;
        asm("mov.b64 {%0, %1}, %2;" : "=f"(xlo), "=f"(xhi) : "l"(x2[j]));
        float e0 = eb[2 * j];
        float e1 = eb[2 * j + 1];
        q[(2 * j)     * SPATIAL] = e0;   // coalesced across warp (same c, s+lane)
        q[(2 * j + 1) * SPATIAL] = e1;
        float d0 = e0 - xlo, d1 = e1 - xhi;
        lsum += d0 * d0 + d1 * d1;
    }

    out[OUT_IDX_OFF + n] = (float)bestk;

    // loss = COMMITMENT_COST * mean((q - x)^2): scale contribution, reduce.
    lsum *= 0.25f / (float)Q_ELEMS;
#pragma unroll
    for (int off = 16; off > 0; off >>= 1)
        lsum += __shfl_down_sync(0xffffffffu, lsum, off);
    // one atomic per warp (16 per block, 8192 total)
    if ((threadIdx.x & 31) == 0) atomicAdd(out + OUT_LOSS_OFF, lsum);
}

// ---------------------------------------------------------------------------
extern "C" void kernel_launch(void* const* d_in, const int* in_sizes, int n_in,
                              void* d_out, int out_size) {
    const float* x_in = (const float*)d_in[0];   // inputs  [16,64,64,64]
    const float* emb  = (const float*)d_in[1];   // embedding [1024,64]
    float* out = (float*)d_out;                  // [1 + 4194304 + 65536] f32

    vq_init_kernel<<<1, 32>>>(out);
    vq_ebias_kernel<<<NCODES / 256, 256>>>(emb);
    vq_main_kernel<<<NPOS / 128, 128>>>(x_in, emb, out);
}

// round 8
// speedup vs baseline: 2.9502x; 2.9502x over previous
#include <cuda_runtime.h>
#include <cuda_fp16.h>
#include <cstdint>

// ---------------- problem constants ----------------
#define SPATIAL   4096
#define DIM       64
#define NCODES    1024
#define Q_ELEMS   4194304
#define OUT_LOSS_OFF 0
#define OUT_Q_OFF    1
#define OUT_IDX_OFF  (1 + Q_ELEMS)

#define TILE_M    128           // positions per CTA
#define CHUNK     128           // codes per smem chunk
#define NCHUNKS   (NCODES / CHUNK)
#define ESTRIDE   72            // halves per row (144B): bank map 4g+q -> conflict-free

// smem layout (byte offsets into extern shared)
#define SM_AHI  0               // [128][72] half  = 18432 B
#define SM_ALO  18432
#define SM_EHI  36864
#define SM_ELO  55296
#define SM_NEB  73728           // 128 floats (-0.5||e||^2 chunk)
#define SM_RED  74240           // 16 floats: [0..7] sum x^2 per warp, [8..15] sum v_best
#define SM_BK   74304           // 128 ints (bestk per position)
#define SMEM_BYTES 74816

// ---------------- device scratch (pre-split, padded E) ----------------
__device__ __align__(16) __half g_ehi[NCODES * ESTRIDE];
__device__ __align__(16) __half g_elo[NCODES * ESTRIDE];
__device__ float g_neb[NCODES];     // -0.5 * ||e_k||^2

// ---------------- mma.sync m16n8k16 f16 -> f32 ----------------
__device__ __forceinline__ void mma16816(float& d0, float& d1, float& d2, float& d3,
                                         uint32_t a0, uint32_t a1, uint32_t a2, uint32_t a3,
                                         uint32_t b0, uint32_t b1) {
    asm volatile("mma.sync.aligned.m16n8k16.row.col.f32.f16.f16.f32 "
                 "{%0,%1,%2,%3}, {%4,%5,%6,%7}, {%8,%9}, {%0,%1,%2,%3};"
                 : "+f"(d0), "+f"(d1), "+f"(d2), "+f"(d3)
                 : "r"(a0), "r"(a1), "r"(a2), "r"(a3), "r"(b0), "r"(b1));
}

// ---------------------------------------------------------------------------
// Kernel 0: zero the loss slot
// ---------------------------------------------------------------------------
__global__ void vq_init_kernel(float* out) {
    if (threadIdx.x == 0 && blockIdx.x == 0) out[OUT_LOSS_OFF] = 0.0f;
}

// ---------------------------------------------------------------------------
// Kernel 1: split E into (hi, lo) f16 with padded rows; neb = -0.5||e||^2
// ---------------------------------------------------------------------------
__global__ void vq_prep_kernel(const float* __restrict__ emb) {
    int r = blockIdx.x * blockDim.x + threadIdx.x;
    if (r >= NCODES) return;
    const float* e = emb + (size_t)r * DIM;
    float s = 0.0f;
#pragma unroll
    for (int c = 0; c < DIM; c++) {
        float v = e[c];
        s += v * v;
        __half h = __float2half_rn(v);
        __half l = __float2half_rn(v - __half2float(h));
        g_ehi[r * ESTRIDE + c] = h;
        g_elo[r * ESTRIDE + c] = l;
    }
    g_neb[r] = -0.5f * s;
}

// ---------------------------------------------------------------------------
// Kernel 2: fused HMMA GEMM + argmin + gather + loss
// ---------------------------------------------------------------------------
__global__ void __launch_bounds__(256, 2) vq_main_kernel(
    const float* __restrict__ x_in,   // [16,64,64,64] NCHW
    const float* __restrict__ emb,    // [1024,64] f32
    float* __restrict__ out)
{
    extern __shared__ char sm[];
    __half* aHi = (__half*)(sm + SM_AHI);
    __half* aLo = (__half*)(sm + SM_ALO);
    __half* eHi = (__half*)(sm + SM_EHI);
    __half* eLo = (__half*)(sm + SM_ELO);
    float*  sneb = (float*)(sm + SM_NEB);
    float*  sred = (float*)(sm + SM_RED);
    int*    sbk  = (int*)(sm + SM_BK);

    const int t    = threadIdx.x;
    const int lane = t & 31;
    const int w    = t >> 5;          // warp 0..7
    const int g    = lane >> 2;       // 0..7
    const int q    = lane & 3;        // 0..3
    const int tile = blockIdx.x;
    const int b_idx = tile >> 5;
    const int s0    = (tile & 31) * TILE_M;
    const float* xbase = x_in + (size_t)b_idx * (DIM * SPATIAL) + s0;

    // --- Phase 1: stage X tile as split f16, accumulate sum(x^2) ---
    {
        int p = t & 127, ch = t >> 7;   // position, c-half
        const float* xp = xbase + p;
        float n2 = 0.0f;
#pragma unroll
        for (int i = 0; i < 32; i++) {
            int c = ch * 32 + i;
            float v = xp[c * SPATIAL];
            n2 += v * v;
            __half h = __float2half_rn(v);
            __half l = __float2half_rn(v - __half2float(h));
            aHi[p * ESTRIDE + c] = h;
            aLo[p * ESTRIDE + c] = l;
        }
#pragma unroll
        for (int off = 16; off > 0; off >>= 1)
            n2 += __shfl_down_sync(0xffffffffu, n2, off);
        if (lane == 0) sred[w] = n2;   // two warps share each c-half; slots distinct per warp
    }
    __syncthreads();

    // --- Load A fragments (resident for whole kernel) ---
    const int m0 = w * 16;
    uint32_t AH[4][4], AL[4][4];
    {
        const uint32_t r0 = (uint32_t)(m0 + g) * ESTRIDE;
        const uint32_t r8 = r0 + 8 * ESTRIDE;
#pragma unroll
        for (int ks = 0; ks < 4; ks++) {
            int c0 = 16 * ks + 2 * q;
            AH[ks][0] = *(const uint32_t*)&aHi[r0 + c0];
            AH[ks][1] = *(const uint32_t*)&aHi[r8 + c0];
            AH[ks][2] = *(const uint32_t*)&aHi[r0 + c0 + 8];
            AH[ks][3] = *(const uint32_t*)&aHi[r8 + c0 + 8];
            AL[ks][0] = *(const uint32_t*)&aLo[r0 + c0];
            AL[ks][1] = *(const uint32_t*)&aLo[r8 + c0];
            AL[ks][2] = *(const uint32_t*)&aLo[r0 + c0 + 8];
            AL[ks][3] = *(const uint32_t*)&aLo[r8 + c0 + 8];
        }
    }

    // --- Main loop: stream E chunks, mma, running argmax of (x.e - 0.5||e||^2) ---
    float bv0 = -3.402823466e38f, bv1 = -3.402823466e38f;
    int   bk0 = 0, bk1 = 0;

    for (int chnk = 0; chnk < NCHUNKS; chnk++) {
        __syncthreads();   // previous chunk's compute done before overwrite
        {
            const uint4* srcH = (const uint4*)(g_ehi + (size_t)chnk * CHUNK * ESTRIDE);
            const uint4* srcL = (const uint4*)(g_elo + (size_t)chnk * CHUNK * ESTRIDE);
            uint4* dH = (uint4*)eHi;
            uint4* dL = (uint4*)eLo;
            for (int i = t; i < (CHUNK * ESTRIDE * 2) / 16; i += 256) {
                dH[i] = srcH[i];
                dL[i] = srcL[i];
            }
            if (t < CHUNK) sneb[t] = g_neb[chnk * CHUNK + t];
        }
        __syncthreads();

        const int kbase = chnk * CHUNK;
#pragma unroll 2
        for (int n8 = 0; n8 < CHUNK / 8; n8++) {
            const int n0 = n8 * 8;
            float2 nb = *(const float2*)&sneb[n0 + 2 * q];
            float c0 = nb.x, c1 = nb.y, c2 = nb.x, c3 = nb.y;   // D init = -0.5||e||^2
            const uint32_t boff = (uint32_t)(n0 + g) * ESTRIDE;
#pragma unroll
            for (int ks = 0; ks < 4; ks++) {
                int cc = 16 * ks + 2 * q;
                uint32_t bh0 = *(const uint32_t*)&eHi[boff + cc];
                uint32_t bh1 = *(const uint32_t*)&eHi[boff + cc + 8];
                uint32_t bl0 = *(const uint32_t*)&eLo[boff + cc];
                uint32_t bl1 = *(const uint32_t*)&eLo[boff + cc + 8];
                mma16816(c0, c1, c2, c3, AH[ks][0], AH[ks][1], AH[ks][2], AH[ks][3], bh0, bh1);
                mma16816(c0, c1, c2, c3, AH[ks][0], AH[ks][1], AH[ks][2], AH[ks][3], bl0, bl1);
                mma16816(c0, c1, c2, c3, AL[ks][0], AL[ks][1], AL[ks][2], AL[ks][3], bh0, bh1);
            }
            const int k0 = kbase + n0 + 2 * q;
            if (c0 > bv0) { bv0 = c0; bk0 = k0; }
            if (c1 > bv0) { bv0 = c1; bk0 = k0 + 1; }
            if (c2 > bv1) { bv1 = c2; bk1 = k0; }
            if (c3 > bv1) { bv1 = c3; bk1 = k0 + 1; }
        }
    }

    // --- Quad reduce (across q lanes); tie-break to smaller k (first occurrence) ---
#pragma unroll
    for (int m = 1; m < 4; m <<= 1) {
        float v = __shfl_xor_sync(0xffffffffu, bv0, m);
        int   k = __shfl_xor_sync(0xffffffffu, bk0, m);
        if (v > bv0 || (v == bv0 && k < bk0)) { bv0 = v; bk0 = k; }
        v = __shfl_xor_sync(0xffffffffu, bv1, m);
        k = __shfl_xor_sync(0xffffffffu, bk1, m);
        if (v > bv1 || (v == bv1 && k < bk1)) { bv1 = v; bk1 = k; }
    }
    {
        float vsum = (q == 0) ? (bv0 + bv1) : 0.0f;
#pragma unroll
        for (int off = 16; off > 0; off >>= 1)
            vsum += __shfl_down_sync(0xffffffffu, vsum, off);
        if (lane == 0) sred[8 + w] = vsum;
        if (q == 0) { sbk[m0 + g] = bk0; sbk[m0 + g + 8] = bk1; }
    }
    __syncthreads();

    // --- Epilogue: indices, quantized gather (coalesced stores), loss ---
    {
        int p = t & 127, ch = t >> 7;
        int bk = sbk[p];
        if (ch == 0) out[OUT_IDX_OFF + tile * TILE_M + p] = (float)bk;
        const float4* er = (const float4*)(emb + (size_t)bk * DIM) + ch * 8;
        float* qo = out + OUT_Q_OFF + (size_t)b_idx * (DIM * SPATIAL) + s0 + p;
#pragma unroll
        for (int j = 0; j < 8; j++) {
            float4 e4 = er[j];
            int c = ch * 32 + 4 * j;
            qo[(c + 0) * SPATIAL] = e4.x;
            qo[(c + 1) * SPATIAL] = e4.y;
            qo[(c + 2) * SPATIAL] = e4.z;
            qo[(c + 3) * SPATIAL] = e4.w;
        }
    }
    if (t == 0) {
        float sx = 0.0f, sv = 0.0f;
#pragma unroll
        for (int i = 0; i < 8; i++) { sx += sred[i]; sv += sred[8 + i]; }
        // sum ||q-x||^2 over tile = sum||x||^2 - 2 * sum v_best
        atomicAdd(out + OUT_LOSS_OFF, (sx - 2.0f * sv) * (0.25f / (float)Q_ELEMS));
    }
}

// ---------------------------------------------------------------------------
extern "C" void kernel_launch(void* const* d_in, const int* in_sizes, int n_in,
                              void* d_out, int out_size) {
    const float* x_in = (const float*)d_in[0];
    const float* emb  = (const float*)d_in[1];
    float* out = (float*)d_out;

    cudaFuncSetAttribute(vq_main_kernel,
                         cudaFuncAttributeMaxDynamicSharedMemorySize, SMEM_BYTES);

    vq_init_kernel<<<1, 32>>>(out);
    vq_prep_kernel<<<NCODES / 256, 256>>>(emb);
    vq_main_kernel<<<(16 * SPATIAL) / TILE_M, 256, SMEM_BYTES>>>(x_in, emb, out);
}

// round 9
// speedup vs baseline: 3.3898x; 1.1490x over previous
#include <cuda_runtime.h>
#include <cuda_fp16.h>
#include <cstdint>

// ---------------- problem constants ----------------
#define SPATIAL   4096
#define DIM       64
#define NCODES    1024
#define Q_ELEMS   4194304
#define OUT_LOSS_OFF 0
#define OUT_Q_OFF    1
#define OUT_IDX_OFF  (1 + Q_ELEMS)

#define TILE_M    128           // positions per CTA
#define CHUNK     128           // codes per smem chunk
#define NCHUNKS   (NCODES / CHUNK)
#define ESTRIDE   72            // halves per row (144B): conflict-free LDS/LDSM

// smem layout (byte offsets). Buf1 (=offset 0) doubles as A staging:
// A fragments are extracted to registers before buf1 is first overwritten.
#define BUF1_OFF   0u           // hi 18432 + lo 18432 = 36864 B
#define BUF0_OFF   36864u
#define HALF_BUF   18432u
#define SM_NEB     73728        // 2 x 128 floats
#define SM_RED     74752        // 16 floats
#define SM_BK      74816        // 128 ints
#define SMEM_BYTES 75392

// ---------------- device scratch (pre-split, padded E) ----------------
__device__ __align__(16) __half g_ehi[NCODES * ESTRIDE];
__device__ __align__(16) __half g_elo[NCODES * ESTRIDE];
__device__ float g_neb[NCODES];     // -0.5 * ||e_k||^2

// ---------------- PTX helpers ----------------
__device__ __forceinline__ uint32_t smem_u32(const void* p) {
    uint32_t a;
    asm("{ .reg .u64 t; cvta.to.shared.u64 t, %1; cvt.u32.u64 %0, t; }" : "=r"(a) : "l"(p));
    return a;
}
#define CP16(dst, src)  asm volatile("cp.async.cg.shared.global [%0], [%1], 16;" :: "r"(dst), "l"(src))
#define CP_COMMIT()     asm volatile("cp.async.commit_group;" ::: "memory")
#define CP_WAIT0()      asm volatile("cp.async.wait_group 0;" ::: "memory")

__device__ __forceinline__ void ldsm_x4(uint32_t& r0, uint32_t& r1, uint32_t& r2,
                                        uint32_t& r3, uint32_t addr) {
    asm volatile("ldmatrix.sync.aligned.m8n8.x4.shared.b16 {%0,%1,%2,%3}, [%4];"
                 : "=r"(r0), "=r"(r1), "=r"(r2), "=r"(r3) : "r"(addr));
}
// D = A*B + {cx,cy,cx,cy}   (bias-init first mma of each chain)
__device__ __forceinline__ void mma_init(float& d0, float& d1, float& d2, float& d3,
                                         uint32_t a0, uint32_t a1, uint32_t a2, uint32_t a3,
                                         uint32_t b0, uint32_t b1, float cx, float cy) {
    asm volatile("mma.sync.aligned.m16n8k16.row.col.f32.f16.f16.f32 "
                 "{%0,%1,%2,%3}, {%4,%5,%6,%7}, {%8,%9}, {%10,%11,%10,%11};"
                 : "=f"(d0), "=f"(d1), "=f"(d2), "=f"(d3)
                 : "r"(a0), "r"(a1), "r"(a2), "r"(a3), "r"(b0), "r"(b1),
                   "f"(cx), "f"(cy));
}
__device__ __forceinline__ void mma_acc(float& d0, float& d1, float& d2, float& d3,
                                        uint32_t a0, uint32_t a1, uint32_t a2, uint32_t a3,
                                        uint32_t b0, uint32_t b1) {
    asm volatile("mma.sync.aligned.m16n8k16.row.col.f32.f16.f16.f32 "
                 "{%0,%1,%2,%3}, {%4,%5,%6,%7}, {%8,%9}, {%0,%1,%2,%3};"
                 : "+f"(d0), "+f"(d1), "+f"(d2), "+f"(d3)
                 : "r"(a0), "r"(a1), "r"(a2), "r"(a3), "r"(b0), "r"(b1));
}

// ---------------------------------------------------------------------------
// Kernel 1: split E into (hi, lo) f16 with padded rows; neb; zero loss slot.
// ---------------------------------------------------------------------------
__global__ void vq_prep_kernel(const float* __restrict__ emb, float* __restrict__ out) {
    int r = blockIdx.x * blockDim.x + threadIdx.x;
    if (r == 0) out[OUT_LOSS_OFF] = 0.0f;
    if (r >= NCODES) return;
    const float* e = emb + (size_t)r * DIM;
    float s = 0.0f;
#pragma unroll
    for (int c = 0; c < DIM; c++) {
        float v = e[c];
        s += v * v;
        __half h = __float2half_rn(v);
        __half l = __float2half_rn(v - __half2float(h));
        g_ehi[r * ESTRIDE + c] = h;
        g_elo[r * ESTRIDE + c] = l;
    }
    g_neb[r] = -0.5f * s;
}

// ---------------------------------------------------------------------------
// Chunk copy: E chunk c (hi+lo, 36864 B) + neb (512 B) via cp.async 16B.
// ---------------------------------------------------------------------------
__device__ __forceinline__ void copy_chunk(uint32_t smb, int c, int t) {
    const uint32_t off = (c & 1) ? BUF1_OFF : BUF0_OFF;
    const char* srcH = (const char*)(g_ehi + (size_t)c * CHUNK * ESTRIDE);
    const char* srcL = (const char*)(g_elo + (size_t)c * CHUNK * ESTRIDE);
    const uint32_t dH = smb + off;
    const uint32_t dL = smb + off + HALF_BUF;
#pragma unroll
    for (int i = t; i < 1152; i += 256) {
        CP16(dH + (uint32_t)i * 16u, srcH + (size_t)i * 16);
        CP16(dL + (uint32_t)i * 16u, srcL + (size_t)i * 16);
    }
    if (t < 32)
        CP16(smb + SM_NEB + (uint32_t)(c & 1) * 512u + (uint32_t)t * 16u,
             (const char*)(g_neb + c * CHUNK) + (size_t)t * 16);
}

// ---------------------------------------------------------------------------
// Kernel 2: fused HMMA GEMM + argmin + gather + loss (double-buffered)
// ---------------------------------------------------------------------------
__global__ void __launch_bounds__(256, 2) vq_main_kernel(
    const float* __restrict__ x_in,   // [16,64,64,64] NCHW
    const float* __restrict__ emb,    // [1024,64] f32
    float* __restrict__ out)
{
    extern __shared__ char sm[];
    const uint32_t smb = smem_u32(sm);
    __half* aHi = (__half*)(sm + BUF1_OFF);             // A staging == buf1
    __half* aLo = (__half*)(sm + BUF1_OFF + HALF_BUF);
    float*  sred = (float*)(sm + SM_RED);
    int*    sbk  = (int*)(sm + SM_BK);

    const int t    = threadIdx.x;
    const int lane = t & 31;
    const int w    = t >> 5;
    const int g    = lane >> 2;
    const int q    = lane & 3;
    const int tile = blockIdx.x;
    const int b_idx = tile >> 5;
    const int s0    = (tile & 31) * TILE_M;
    const float* xbase = x_in + (size_t)b_idx * (DIM * SPATIAL) + s0;

    // kick off chunk 0 load into buf0 (overlaps X staging below)
    copy_chunk(smb, 0, t);
    CP_COMMIT();

    // --- stage X tile as split f16 into buf1 region; accumulate sum(x^2) ---
    {
        int p = t & 127, ch = t >> 7;
        const float* xp = xbase + p;
        float n2 = 0.0f;
#pragma unroll
        for (int i = 0; i < 32; i++) {
            int c = ch * 32 + i;
            float v = xp[c * SPATIAL];
            n2 += v * v;
            __half h = __float2half_rn(v);
            __half l = __float2half_rn(v - __half2float(h));
            aHi[p * ESTRIDE + c] = h;
            aLo[p * ESTRIDE + c] = l;
        }
#pragma unroll
        for (int off = 16; off > 0; off >>= 1)
            n2 += __shfl_down_sync(0xffffffffu, n2, off);
        if (lane == 0) sred[w] = n2;
    }
    __syncthreads();

    // --- load A fragments (resident); then buf1 is free for E chunks ---
    const int m0 = w * 16;
    uint32_t AH[4][4], AL[4][4];
    {
        const uint32_t r0 = (uint32_t)(m0 + g) * ESTRIDE;
        const uint32_t r8 = r0 + 8 * ESTRIDE;
#pragma unroll
        for (int ks = 0; ks < 4; ks++) {
            int c0 = 16 * ks + 2 * q;
            AH[ks][0] = *(const uint32_t*)&aHi[r0 + c0];
            AH[ks][1] = *(const uint32_t*)&aHi[r8 + c0];
            AH[ks][2] = *(const uint32_t*)&aHi[r0 + c0 + 8];
            AH[ks][3] = *(const uint32_t*)&aHi[r8 + c0 + 8];
            AL[ks][0] = *(const uint32_t*)&aLo[r0 + c0];
            AL[ks][1] = *(const uint32_t*)&aLo[r8 + c0];
            AL[ks][2] = *(const uint32_t*)&aLo[r0 + c0 + 8];
            AL[ks][3] = *(const uint32_t*)&aLo[r8 + c0 + 8];
        }
    }
    __syncthreads();   // all fragments extracted before buf1 is overwritten

    // per-lane ldmatrix base offset within a buffer (16B-aligned)
    const uint32_t lmoff = (uint32_t)(((lane & 7) * ESTRIDE + (lane >> 3) * 8) * 2);

    float bv0 = -3.402823466e38f, bv1 = -3.402823466e38f;
    int   bk0 = 0, bk1 = 0;

    for (int c = 0; c < NCHUNKS; c++) {
        CP_WAIT0();            // chunk c landed
        __syncthreads();       // visible to all; all warps done with chunk c-1
        if (c + 1 < NCHUNKS) { copy_chunk(smb, c + 1, t); CP_COMMIT(); }

        const uint32_t boff = smb + ((c & 1) ? BUF1_OFF : BUF0_OFF);
        const uint32_t bhi = boff + lmoff;
        const uint32_t blo = boff + HALF_BUF + lmoff;
        const float* sneb = (const float*)(sm + SM_NEB + (c & 1) * 512);
        const int kbase = c * CHUNK;

#pragma unroll 2
        for (int n8 = 0; n8 < CHUNK / 8; n8++) {
            const uint32_t adv = (uint32_t)n8 * (8u * ESTRIDE * 2u);
            uint32_t h0, h1, h2, h3, h4, h5, h6, h7;
            uint32_t l0, l1, l2, l3, l4, l5, l6, l7;
            ldsm_x4(h0, h1, h2, h3, bhi + adv);
            ldsm_x4(h4, h5, h6, h7, bhi + adv + 64u);
            ldsm_x4(l0, l1, l2, l3, blo + adv);
            ldsm_x4(l4, l5, l6, l7, blo + adv + 64u);
            float2 nb = *(const float2*)&sneb[n8 * 8 + 2 * q];

            float d0, d1, d2, d3;   // single 12-deep chain, bias-initialized
            mma_init(d0, d1, d2, d3, AH[0][0], AH[0][1], AH[0][2], AH[0][3], h0, h1, nb.x, nb.y);
            mma_acc (d0, d1, d2, d3, AH[1][0], AH[1][1], AH[1][2], AH[1][3], h2, h3);
            mma_acc (d0, d1, d2, d3, AH[2][0], AH[2][1], AH[2][2], AH[2][3], h4, h5);
            mma_acc (d0, d1, d2, d3, AH[3][0], AH[3][1], AH[3][2], AH[3][3], h6, h7);
            mma_acc (d0, d1, d2, d3, AH[0][0], AH[0][1], AH[0][2], AH[0][3], l0, l1);
            mma_acc (d0, d1, d2, d3, AH[1][0], AH[1][1], AH[1][2], AH[1][3], l2, l3);
            mma_acc (d0, d1, d2, d3, AH[2][0], AH[2][1], AH[2][2], AH[2][3], l4, l5);
            mma_acc (d0, d1, d2, d3, AH[3][0], AH[3][1], AH[3][2], AH[3][3], l6, l7);
            mma_acc (d0, d1, d2, d3, AL[0][0], AL[0][1], AL[0][2], AL[0][3], h0, h1);
            mma_acc (d0, d1, d2, d3, AL[1][0], AL[1][1], AL[1][2], AL[1][3], h2, h3);
            mma_acc (d0, d1, d2, d3, AL[2][0], AL[2][1], AL[2][2], AL[2][3], h4, h5);
            mma_acc (d0, d1, d2, d3, AL[3][0], AL[3][1], AL[3][2], AL[3][3], h6, h7);

            const int k0 = kbase + n8 * 8 + 2 * q;
            if (d0 > bv0) { bv0 = d0; bk0 = k0; }
            if (d1 > bv0) { bv0 = d1; bk0 = k0 + 1; }
            if (d2 > bv1) { bv1 = d2; bk1 = k0; }
            if (d3 > bv1) { bv1 = d3; bk1 = k0 + 1; }
        }
    }

    // --- quad reduce (tie-break to smaller k = first occurrence) ---
#pragma unroll
    for (int m = 1; m < 4; m <<= 1) {
        float v = __shfl_xor_sync(0xffffffffu, bv0, m);
        int   k = __shfl_xor_sync(0xffffffffu, bk0, m);
        if (v > bv0 || (v == bv0 && k < bk0)) { bv0 = v; bk0 = k; }
        v = __shfl_xor_sync(0xffffffffu, bv1, m);
        k = __shfl_xor_sync(0xffffffffu, bk1, m);
        if (v > bv1 || (v == bv1 && k < bk1)) { bv1 = v; bk1 = k; }
    }
    {
        float vsum = (q == 0) ? (bv0 + bv1) : 0.0f;
#pragma unroll
        for (int off = 16; off > 0; off >>= 1)
            vsum += __shfl_down_sync(0xffffffffu, vsum, off);
        if (lane == 0) sred[8 + w] = vsum;
        if (q == 0) { sbk[m0 + g] = bk0; sbk[m0 + g + 8] = bk1; }
    }
    __syncthreads();

    // --- epilogue: indices, quantized gather (coalesced stores), loss ---
    {
        int p = t & 127, ch = t >> 7;
        int bk = sbk[p];
        if (ch == 0) out[OUT_IDX_OFF + tile * TILE_M + p] = (float)bk;
        const float4* er = (const float4*)(emb + (size_t)bk * DIM) + ch * 8;
        float* qo = out + OUT_Q_OFF + (size_t)b_idx * (DIM * SPATIAL) + s0 + p;
#pragma unroll
        for (int j = 0; j < 8; j++) {
            float4 e4 = er[j];
            int cc = ch * 32 + 4 * j;
            qo[(cc + 0) * SPATIAL] = e4.x;
            qo[(cc + 1) * SPATIAL] = e4.y;
            qo[(cc + 2) * SPATIAL] = e4.z;
            qo[(cc + 3) * SPATIAL] = e4.w;
        }
    }
    if (t == 0) {
        float sx = 0.0f, sv = 0.0f;
#pragma unroll
        for (int i = 0; i < 8; i++) { sx += sred[i]; sv += sred[8 + i]; }
        atomicAdd(out + OUT_LOSS_OFF, (sx - 2.0f * sv) * (0.25f / (float)Q_ELEMS));
    }
}

// ---------------------------------------------------------------------------
extern "C" void kernel_launch(void* const* d_in, const int* in_sizes, int n_in,
                              void* d_out, int out_size) {
    const float* x_in = (const float*)d_in[0];
    const float* emb  = (const float*)d_in[1];
    float* out = (float*)d_out;

    cudaFuncSetAttribute(vq_main_kernel,
                         cudaFuncAttributeMaxDynamicSharedMemorySize, SMEM_BYTES);

    vq_prep_kernel<<<NCODES / 256, 256>>>(emb, out);
    vq_main_kernel<<<(16 * SPATIAL) / TILE_M, 256, SMEM_BYTES>>>(x_in, emb, out);
}

// round 10
// speedup vs baseline: 3.5271x; 1.0405x over previous
#include <cuda_runtime.h>
#include <cuda_fp16.h>
#include <cstdint>

// ---------------- problem constants ----------------
#define SPATIAL   4096
#define DIM       64
#define NCODES    1024
#define Q_ELEMS   4194304
#define OUT_LOSS_OFF 0
#define OUT_Q_OFF    1
#define OUT_IDX_OFF  (1 + Q_ELEMS)

#define TILE_M    256           // positions per CTA (2 m16 slabs per warp)
#define CHUNK     128           // codes per smem chunk
#define NCHUNKS   (NCODES / CHUNK)
#define ESTRIDE   72            // halves per row (144B): conflict-free LDS/LDSM

// smem layout (byte offsets). Buf1 (=offset 0) doubles as A staging (2 passes).
#define BUF1_OFF   0u           // hi 18432 + lo 18432 = 36864 B
#define BUF0_OFF   36864u
#define HALF_BUF   18432u
#define SM_NEB     73728        // 2 x 128 floats (1024 B)
#define SM_RED     74752        // 16 floats
#define SM_BK      74816        // 256 ints (1024 B)
#define SMEM_BYTES 75840

// ---------------- device scratch (pre-split, padded E) ----------------
__device__ __align__(16) __half g_ehi[NCODES * ESTRIDE];
__device__ __align__(16) __half g_elo[NCODES * ESTRIDE];
__device__ float g_neb[NCODES];     // -0.5 * ||e_k||^2

// ---------------- PTX helpers ----------------
__device__ __forceinline__ uint32_t smem_u32(const void* p) {
    uint32_t a;
    asm("{ .reg .u64 t; cvta.to.shared.u64 t, %1; cvt.u32.u64 %0, t; }" : "=r"(a) : "l"(p));
    return a;
}
#define CP16(dst, src)  asm volatile("cp.async.cg.shared.global [%0], [%1], 16;" :: "r"(dst), "l"(src))
#define CP_COMMIT()     asm volatile("cp.async.commit_group;" ::: "memory")
#define CP_WAIT0()      asm volatile("cp.async.wait_group 0;" ::: "memory")

__device__ __forceinline__ void ldsm_x4(uint32_t& r0, uint32_t& r1, uint32_t& r2,
                                        uint32_t& r3, uint32_t addr) {
    asm volatile("ldmatrix.sync.aligned.m8n8.x4.shared.b16 {%0,%1,%2,%3}, [%4];"
                 : "=r"(r0), "=r"(r1), "=r"(r2), "=r"(r3) : "r"(addr));
}
__device__ __forceinline__ void mma_init(float& d0, float& d1, float& d2, float& d3,
                                         uint32_t a0, uint32_t a1, uint32_t a2, uint32_t a3,
                                         uint32_t b0, uint32_t b1, float cx, float cy) {
    asm volatile("mma.sync.aligned.m16n8k16.row.col.f32.f16.f16.f32 "
                 "{%0,%1,%2,%3}, {%4,%5,%6,%7}, {%8,%9}, {%10,%11,%10,%11};"
                 : "=f"(d0), "=f"(d1), "=f"(d2), "=f"(d3)
                 : "r"(a0), "r"(a1), "r"(a2), "r"(a3), "r"(b0), "r"(b1),
                   "f"(cx), "f"(cy));
}
__device__ __forceinline__ void mma_acc(float& d0, float& d1, float& d2, float& d3,
                                        uint32_t a0, uint32_t a1, uint32_t a2, uint32_t a3,
                                        uint32_t b0, uint32_t b1) {
    asm volatile("mma.sync.aligned.m16n8k16.row.col.f32.f16.f16.f32 "
                 "{%0,%1,%2,%3}, {%4,%5,%6,%7}, {%8,%9}, {%0,%1,%2,%3};"
                 : "+f"(d0), "+f"(d1), "+f"(d2), "+f"(d3)
                 : "r"(a0), "r"(a1), "r"(a2), "r"(a3), "r"(b0), "r"(b1));
}

// ---------------------------------------------------------------------------
// Kernel 1: split E into (hi, lo) f16 with padded rows; neb; zero loss slot.
// ---------------------------------------------------------------------------
__global__ void vq_prep_kernel(const float* __restrict__ emb, float* __restrict__ out) {
    int r = blockIdx.x * blockDim.x + threadIdx.x;
    if (r == 0) out[OUT_LOSS_OFF] = 0.0f;
    if (r >= NCODES) return;
    const float* e = emb + (size_t)r * DIM;
    float s = 0.0f;
#pragma unroll
    for (int c = 0; c < DIM; c++) {
        float v = e[c];
        s += v * v;
        __half h = __float2half_rn(v);
        __half l = __float2half_rn(v - __half2float(h));
        g_ehi[r * ESTRIDE + c] = h;
        g_elo[r * ESTRIDE + c] = l;
    }
    g_neb[r] = -0.5f * s;
}

// ---------------------------------------------------------------------------
// Chunk copy: E chunk c (hi+lo, 36864 B) + neb (512 B) via cp.async 16B.
// ---------------------------------------------------------------------------
__device__ __forceinline__ void copy_chunk(uint32_t smb, int c, int t) {
    const uint32_t off = (c & 1) ? BUF1_OFF : BUF0_OFF;
    const char* srcH = (const char*)(g_ehi + (size_t)c * CHUNK * ESTRIDE);
    const char* srcL = (const char*)(g_elo + (size_t)c * CHUNK * ESTRIDE);
    const uint32_t dH = smb + off;
    const uint32_t dL = smb + off + HALF_BUF;
#pragma unroll
    for (int i = t; i < 1152; i += 256) {
        CP16(dH + (uint32_t)i * 16u, srcH + (size_t)i * 16);
        CP16(dL + (uint32_t)i * 16u, srcL + (size_t)i * 16);
    }
    if (t < 32)
        CP16(smb + SM_NEB + (uint32_t)(c & 1) * 512u + (uint32_t)t * 16u,
             (const char*)(g_neb + c * CHUNK) + (size_t)t * 16);
}

// ---------------------------------------------------------------------------
// Kernel 2: fused HMMA GEMM + argmin + gather + loss.
// 256 positions/CTA, 8 warps, each warp computes 2 m16 slabs sharing B frags.
// ---------------------------------------------------------------------------
__global__ void __launch_bounds__(256, 2) vq_main_kernel(
    const float* __restrict__ x_in,   // [16,64,64,64] NCHW
    const float* __restrict__ emb,    // [1024,64] f32
    float* __restrict__ out)
{
    extern __shared__ char sm[];
    const uint32_t smb = smem_u32(sm);
    __half* aHi = (__half*)(sm + BUF1_OFF);             // A staging == buf1
    __half* aLo = (__half*)(sm + BUF1_OFF + HALF_BUF);
    float*  sred = (float*)(sm + SM_RED);
    int*    sbk  = (int*)(sm + SM_BK);

    const int t    = threadIdx.x;
    const int lane = t & 31;
    const int w    = t >> 5;
    const int g    = lane >> 2;
    const int q    = lane & 3;
    const int tile = blockIdx.x;
    const int b_idx = tile >> 4;               // 16 tiles per image
    const int s0    = (tile & 15) * TILE_M;
    const float* xbase = x_in + (size_t)b_idx * (DIM * SPATIAL) + s0;

    // kick off chunk 0 load into buf0 (overlaps X staging below)
    copy_chunk(smb, 0, t);
    CP_COMMIT();

    // --- stage X tile in 2 passes of 128 positions; extract A frags per slab ---
    const int m0 = w * 16;
    uint32_t AH[2][4][4], AL[2][4][4];
    float n2 = 0.0f;
#pragma unroll
    for (int pass = 0; pass < 2; pass++) {
        {
            int p = t & 127, ch = t >> 7;
            const float* xp = xbase + pass * 128 + p;
#pragma unroll
            for (int i = 0; i < 32; i++) {
                int c = ch * 32 + i;
                float v = xp[c * SPATIAL];
                n2 += v * v;
                __half h = __float2half_rn(v);
                __half l = __float2half_rn(v - __half2float(h));
                aHi[p * ESTRIDE + c] = h;
                aLo[p * ESTRIDE + c] = l;
            }
        }
        __syncthreads();
        {
            const uint32_t r0 = (uint32_t)(m0 + g) * ESTRIDE;
            const uint32_t r8 = r0 + 8 * ESTRIDE;
#pragma unroll
            for (int ks = 0; ks < 4; ks++) {
                int c0 = 16 * ks + 2 * q;
                AH[pass][ks][0] = *(const uint32_t*)&aHi[r0 + c0];
                AH[pass][ks][1] = *(const uint32_t*)&aHi[r8 + c0];
                AH[pass][ks][2] = *(const uint32_t*)&aHi[r0 + c0 + 8];
                AH[pass][ks][3] = *(const uint32_t*)&aHi[r8 + c0 + 8];
                AL[pass][ks][0] = *(const uint32_t*)&aLo[r0 + c0];
                AL[pass][ks][1] = *(const uint32_t*)&aLo[r8 + c0];
                AL[pass][ks][2] = *(const uint32_t*)&aLo[r0 + c0 + 8];
                AL[pass][ks][3] = *(const uint32_t*)&aLo[r8 + c0 + 8];
            }
        }
        __syncthreads();   // fragments extracted before buf1 is reused
    }
    // fold sum(x^2) now (A staging done)
#pragma unroll
    for (int off = 16; off > 0; off >>= 1)
        n2 += __shfl_down_sync(0xffffffffu, n2, off);
    if (lane == 0) sred[w] = n2;

    // per-lane ldmatrix base offset within a buffer (16B-aligned)
    const uint32_t lmoff = (uint32_t)(((lane & 7) * ESTRIDE + (lane >> 3) * 8) * 2);

    float bv0 = -3.402823466e38f, bv1 = -3.402823466e38f;
    float bv2 = -3.402823466e38f, bv3 = -3.402823466e38f;
    int   bk0 = 0, bk1 = 0, bk2 = 0, bk3 = 0;

    for (int c = 0; c < NCHUNKS; c++) {
        CP_WAIT0();            // chunk c landed
        __syncthreads();       // visible to all; all warps done with chunk c-1
        if (c + 1 < NCHUNKS) { copy_chunk(smb, c + 1, t); CP_COMMIT(); }

        const uint32_t boff = smb + ((c & 1) ? BUF1_OFF : BUF0_OFF);
        const uint32_t bhi = boff + lmoff;
        const uint32_t blo = boff + HALF_BUF + lmoff;
        const float* sneb = (const float*)(sm + SM_NEB + (c & 1) * 512);
        const int kbase = c * CHUNK;

#pragma unroll 2
        for (int n8 = 0; n8 < CHUNK / 8; n8++) {
            const uint32_t adv = (uint32_t)n8 * (8u * ESTRIDE * 2u);
            uint32_t h0, h1, h2, h3, h4, h5, h6, h7;
            uint32_t l0, l1, l2, l3, l4, l5, l6, l7;
            ldsm_x4(h0, h1, h2, h3, bhi + adv);
            ldsm_x4(h4, h5, h6, h7, bhi + adv + 64u);
            ldsm_x4(l0, l1, l2, l3, blo + adv);
            ldsm_x4(l4, l5, l6, l7, blo + adv + 64u);
            float2 nb = *(const float2*)&sneb[n8 * 8 + 2 * q];

            // two independent 12-deep chains (slab 0 / slab 1), shared B frags
            float d0, d1, d2, d3, e0, e1, e2, e3;
            mma_init(d0, d1, d2, d3, AH[0][0][0], AH[0][0][1], AH[0][0][2], AH[0][0][3], h0, h1, nb.x, nb.y);
            mma_init(e0, e1, e2, e3, AH[1][0][0], AH[1][0][1], AH[1][0][2], AH[1][0][3], h0, h1, nb.x, nb.y);
            mma_acc (d0, d1, d2, d3, AH[0][1][0], AH[0][1][1], AH[0][1][2], AH[0][1][3], h2, h3);
            mma_acc (e0, e1, e2, e3, AH[1][1][0], AH[1][1][1], AH[1][1][2], AH[1][1][3], h2, h3);
            mma_acc (d0, d1, d2, d3, AH[0][2][0], AH[0][2][1], AH[0][2][2], AH[0][2][3], h4, h5);
            mma_acc (e0, e1, e2, e3, AH[1][2][0], AH[1][2][1], AH[1][2][2], AH[1][2][3], h4, h5);
            mma_acc (d0, d1, d2, d3, AH[0][3][0], AH[0][3][1], AH[0][3][2], AH[0][3][3], h6, h7);
            mma_acc (e0, e1, e2, e3, AH[1][3][0], AH[1][3][1], AH[1][3][2], AH[1][3][3], h6, h7);
            mma_acc (d0, d1, d2, d3, AH[0][0][0], AH[0][0][1], AH[0][0][2], AH[0][0][3], l0, l1);
            mma_acc (e0, e1, e2, e3, AH[1][0][0], AH[1][0][1], AH[1][0][2], AH[1][0][3], l0, l1);
            mma_acc (d0, d1, d2, d3, AH[0][1][0], AH[0][1][1], AH[0][1][2], AH[0][1][3], l2, l3);
            mma_acc (e0, e1, e2, e3, AH[1][1][0], AH[1][1][1], AH[1][1][2], AH[1][1][3], l2, l3);
            mma_acc (d0, d1, d2, d3, AH[0][2][0], AH[0][2][1], AH[0][2][2], AH[0][2][3], l4, l5);
            mma_acc (e0, e1, e2, e3, AH[1][2][0], AH[1][2][1], AH[1][2][2], AH[1][2][3], l4, l5);
            mma_acc (d0, d1, d2, d3, AH[0][3][0], AH[0][3][1], AH[0][3][2], AH[0][3][3], l6, l7);
            mma_acc (e0, e1, e2, e3, AH[1][3][0], AH[1][3][1], AH[1][3][2], AH[1][3][3], l6, l7);
            mma_acc (d0, d1, d2, d3, AL[0][0][0], AL[0][0][1], AL[0][0][2], AL[0][0][3], h0, h1);
            mma_acc (e0, e1, e2, e3, AL[1][0][0], AL[1][0][1], AL[1][0][2], AL[1][0][3], h0, h1);
            mma_acc (d0, d1, d2, d3, AL[0][1][0], AL[0][1][1], AL[0][1][2], AL[0][1][3], h2, h3);
            mma_acc (e0, e1, e2, e3, AL[1][1][0], AL[1][1][1], AL[1][1][2], AL[1][1][3], h2, h3);
            mma_acc (d0, d1, d2, d3, AL[0][2][0], AL[0][2][1], AL[0][2][2], AL[0][2][3], h4, h5);
            mma_acc (e0, e1, e2, e3, AL[1][2][0], AL[1][2][1], AL[1][2][2], AL[1][2][3], h4, h5);
            mma_acc (d0, d1, d2, d3, AL[0][3][0], AL[0][3][1], AL[0][3][2], AL[0][3][3], h6, h7);
            mma_acc (e0, e1, e2, e3, AL[1][3][0], AL[1][3][1], AL[1][3][2], AL[1][3][3], h6, h7);

            const int k0 = kbase + n8 * 8 + 2 * q;
            if (d0 > bv0) { bv0 = d0; bk0 = k0; }
            if (d1 > bv0) { bv0 = d1; bk0 = k0 + 1; }
            if (d2 > bv1) { bv1 = d2; bk1 = k0; }
            if (d3 > bv1) { bv1 = d3; bk1 = k0 + 1; }
            if (e0 > bv2) { bv2 = e0; bk2 = k0; }
            if (e1 > bv2) { bv2 = e1; bk2 = k0 + 1; }
            if (e2 > bv3) { bv3 = e2; bk3 = k0; }
            if (e3 > bv3) { bv3 = e3; bk3 = k0 + 1; }
        }
    }

    // --- quad reduce (tie-break to smaller k = first occurrence) ---
#pragma unroll
    for (int m = 1; m < 4; m <<= 1) {
        float v; int k;
        v = __shfl_xor_sync(0xffffffffu, bv0, m); k = __shfl_xor_sync(0xffffffffu, bk0, m);
        if (v > bv0 || (v == bv0 && k < bk0)) { bv0 = v; bk0 = k; }
        v = __shfl_xor_sync(0xffffffffu, bv1, m); k = __shfl_xor_sync(0xffffffffu, bk1, m);
        if (v > bv1 || (v == bv1 && k < bk1)) { bv1 = v; bk1 = k; }
        v = __shfl_xor_sync(0xffffffffu, bv2, m); k = __shfl_xor_sync(0xffffffffu, bk2, m);
        if (v > bv2 || (v == bv2 && k < bk2)) { bv2 = v; bk2 = k; }
        v = __shfl_xor_sync(0xffffffffu, bv3, m); k = __shfl_xor_sync(0xffffffffu, bk3, m);
        if (v > bv3 || (v == bv3 && k < bk3)) { bv3 = v; bk3 = k; }
    }
    {
        float vsum = (q == 0) ? (bv0 + bv1 + bv2 + bv3) : 0.0f;
#pragma unroll
        for (int off = 16; off > 0; off >>= 1)
            vsum += __shfl_down_sync(0xffffffffu, vsum, off);
        if (lane == 0) sred[8 + w] = vsum;
        if (q == 0) {
            sbk[m0 + g]             = bk0;
            sbk[m0 + g + 8]         = bk1;
            sbk[128 + m0 + g]       = bk2;
            sbk[128 + m0 + g + 8]   = bk3;
        }
    }
    __syncthreads();

    // --- epilogue: indices, quantized gather (coalesced stores), loss ---
    {
        int p = t;                       // one position per thread
        int bk = sbk[p];
        out[OUT_IDX_OFF + (size_t)b_idx * SPATIAL + s0 + p] = (float)bk;
        const float4* er = (const float4*)(emb + (size_t)bk * DIM);
        float* qo = out + OUT_Q_OFF + (size_t)b_idx * (DIM * SPATIAL) + s0 + p;
#pragma unroll
        for (int j = 0; j < 16; j++) {
            float4 e4 = er[j];
            int cc = 4 * j;
            qo[(cc + 0) * SPATIAL] = e4.x;
            qo[(cc + 1) * SPATIAL] = e4.y;
            qo[(cc + 2) * SPATIAL] = e4.z;
            qo[(cc + 3) * SPATIAL] = e4.w;
        }
    }
    if (t == 0) {
        float sx = 0.0f, sv = 0.0f;
#pragma unroll
        for (int i = 0; i < 8; i++) { sx += sred[i]; sv += sred[8 + i]; }
        atomicAdd(out + OUT_LOSS_OFF, (sx - 2.0f * sv) * (0.25f / (float)Q_ELEMS));
    }
}

// ---------------------------------------------------------------------------
extern "C" void kernel_launch(void* const* d_in, const int* in_sizes, int n_in,
                              void* d_out, int out_size) {
    const float* x_in = (const float*)d_in[0];
    const float* emb  = (const float*)d_in[1];
    float* out = (float*)d_out;

    cudaFuncSetAttribute(vq_main_kernel,
                         cudaFuncAttributeMaxDynamicSharedMemorySize, SMEM_BYTES);

    vq_prep_kernel<<<NCODES / 256, 256>>>(emb, out);
    vq_main_kernel<<<(16 * SPATIAL) / TILE_M, 256, SMEM_BYTES>>>(x_in, emb, out);
}